// round 1
// baseline (speedup 1.0000x reference)
#include <cuda_runtime.h>

#define N_NODES_C 150000
#define N_EDGES_C 300000
#define N_LG_C    600000
#define N_TREE_C  60000
#define HID       256
#define NGRAPH    2048
#define AFD       35
#define BFD       5
#define KIN       40    // AFD + BFD
#define KOUT      291   // AFD + HID

// ---------------- scratch (static device globals; no allocation) ----------------
__device__ float g_msg_input[(size_t)N_EDGES_C * HID];  // 307 MB
__device__ float g_msg      [(size_t)N_EDGES_C * HID];  // 307 MB
__device__ float g_accum    [(size_t)N_EDGES_C * HID];  // 307 MB
__device__ float g_alpha    [(size_t)N_NODES_C * HID];  // 154 MB
__device__ float g_mplus    [(size_t)N_NODES_C * HID];  // 154 MB
__device__ float g_counts   [NGRAPH];

// ---------------- small PTX helpers ----------------
__device__ __forceinline__ unsigned long long pk2(float x, float y) {
    unsigned long long r;
    asm("mov.b64 %0, {%1, %2};" : "=l"(r) : "f"(x), "f"(y));
    return r;
}
__device__ __forceinline__ void upk2(unsigned long long v, float& x, float& y) {
    asm("mov.b64 {%0, %1}, %2;" : "=f"(x), "=f"(y) : "l"(v));
}
// packed fp32x2 FMA (Blackwell-only; 2x FFMA throughput)
__device__ __forceinline__ void ffma2(unsigned long long& d, unsigned long long a, unsigned long long b) {
    asm("fma.rn.f32x2 %0, %1, %2, %0;" : "+l"(d) : "l"(a), "l"(b));
}
// vectorized global reduction (sm_90+): 4 floats per instruction
__device__ __forceinline__ void red4(float* p, float a, float b, float c, float d) {
    asm volatile("red.global.add.v4.f32 [%0], {%1, %2, %3, %4};"
                 :: "l"(p), "f"(a), "f"(b), "f"(c), "f"(d) : "memory");
}

// ---------------- utility kernels ----------------
__global__ void k_zero_alpha() {
    int i = blockIdx.x * 256 + threadIdx.x;           // N_NODES*64 float4
    ((float4*)g_alpha)[i] = make_float4(0.f, 0.f, 0.f, 0.f);
}
__global__ void k_zero_out(float* __restrict__ out) {
    int i = blockIdx.x * 256 + threadIdx.x;           // NGRAPH*64 float4
    ((float4*)out)[i] = make_float4(0.f, 0.f, 0.f, 0.f);
    if (i < NGRAPH) g_counts[i] = 0.f;
}
__global__ void k_copy_mplus() {
    int i = blockIdx.x * 256 + threadIdx.x;           // N_NODES*64 float4
    ((float4*)g_mplus)[i] = ((const float4*)g_alpha)[i];
}
__global__ void k_counts(const int* __restrict__ gids) {
    int v = blockIdx.x * 256 + threadIdx.x;
    if (v < N_NODES_C) atomicAdd(&g_counts[gids[v]], 1.0f);
}
__global__ void k_div(float* __restrict__ out) {
    int i = blockIdx.x * 256 + threadIdx.x;           // NGRAPH*64 float4
    int g = i >> 6;
    float c = fmaxf(g_counts[g], 1.0f);
    float4 v = ((float4*)out)[i];
    v.x /= c; v.y /= c; v.z /= c; v.w /= c;
    ((float4*)out)[i] = v;
}

// node_alpha[tgt[t]] += tree_mess[t]   (64 threads per row, float4 vector red)
__global__ void k_tree_scatter(const float* __restrict__ tree, const int* __restrict__ tgt) {
    int i = blockIdx.x * 256 + threadIdx.x;           // N_TREE*64
    int t = i >> 6, q = i & 63;
    float4 v = ((const float4*)tree)[(size_t)t * 64 + q];
    red4(g_alpha + (size_t)tgt[t] * HID + q * 4, v.x, v.y, v.z, v.w);
}
// accum[e] = node_alpha[edge_src[e]]
__global__ void k_gather_alpha(const int* __restrict__ esrc) {
    int i = blockIdx.x * 256 + threadIdx.x;           // N_EDGES*64
    int e = i >> 6, q = i & 63;
    ((float4*)g_accum)[(size_t)e * 64 + q] = ((const float4*)g_alpha)[(size_t)esrc[e] * 64 + q];
}
// accum[lg_dst[i]] += msg[lg_src[i]]
__global__ void k_lg_scatter(const int* __restrict__ lsrc, const int* __restrict__ ldst) {
    int i = blockIdx.x * 256 + threadIdx.x;           // N_LG*64
    int e = i >> 6, q = i & 63;
    float4 v = ((const float4*)g_msg)[(size_t)lsrc[e] * 64 + q];
    red4(g_accum + (size_t)ldst[e] * HID + q * 4, v.x, v.y, v.z, v.w);
}
// mplus[edge_dst[e]] += msg[e]
__global__ void k_dst_scatter(const int* __restrict__ edst) {
    int i = blockIdx.x * 256 + threadIdx.x;           // N_EDGES*64
    int e = i >> 6, q = i & 63;
    float4 v = ((const float4*)g_msg)[(size_t)e * 64 + q];
    red4(g_mplus + (size_t)edst[e] * HID + q * 4, v.x, v.y, v.z, v.w);
}

// ---------------- msg_input = [node_x[src]; bond_x] @ W_i ; msg = relu ----------------
// One block per 64 edges; each thread owns one output column with W_i column in regs.
__global__ __launch_bounds__(256)
void k_msg_in(const float* __restrict__ node_x, const float* __restrict__ bond_x,
              const float* __restrict__ W_i, const int* __restrict__ esrc) {
    __shared__ float feat[64][KIN];
    int e0 = blockIdx.x * 64;
    int tid = threadIdx.x;
    float w[KIN];
#pragma unroll
    for (int k = 0; k < KIN; k++) w[k] = W_i[k * HID + tid];
    for (int idx = tid; idx < 64 * KIN; idx += 256) {
        int e = idx / KIN, k = idx % KIN;
        int ge = e0 + e;
        float vv = 0.f;
        if (ge < N_EDGES_C)
            vv = (k < AFD) ? node_x[(size_t)esrc[ge] * AFD + k]
                           : bond_x[(size_t)ge * BFD + (k - AFD)];
        feat[e][k] = vv;
    }
    __syncthreads();
    for (int e = 0; e < 64; e++) {
        int ge = e0 + e;
        if (ge >= N_EDGES_C) break;
        float a0 = 0.f, a1 = 0.f;
#pragma unroll
        for (int k = 0; k < KIN; k += 2) {
            a0 = fmaf(feat[e][k],     w[k],     a0);
            a1 = fmaf(feat[e][k + 1], w[k + 1], a1);
        }
        float acc = a0 + a1;
        g_msg_input[(size_t)ge * HID + tid] = acc;
        g_msg[(size_t)ge * HID + tid]       = fmaxf(acc, 0.f);
    }
}

// ---------------- tiled SGEMM (128x128 tile, 256 threads, 8x8/thread, f32x2 FMA) ----------
// MODE 0: msg = relu(msg_input + g_accum @ W_h)            M = N_EDGES, K = 256
// MODE 1: h   = relu([node_x ; g_mplus] @ W_o + b_o),      M = N_NODES, K = 291 (pad 304)
//         then red4 into per-graph sums in `out`.
template<int MODE>
__global__ __launch_bounds__(256, 2)
void k_gemm(const float* __restrict__ B,
            const float* __restrict__ node_x,
            const float* __restrict__ b_o,
            const int*   __restrict__ gids,
            float* __restrict__ out) {
    constexpr int M  = (MODE == 0) ? N_EDGES_C : N_NODES_C;
    constexpr int KT = (MODE == 0) ? 16 : 19;   // k-tiles of 16

    __shared__ float As[16][128];
    __shared__ float Bs[16][128];

    const int tid = threadIdx.x;
    const int tx = tid & 15;
    const int ty = tid >> 4;
    const int m0 = blockIdx.x * 128;
    const int n0 = blockIdx.y * 128;

    unsigned long long c2[4][8];
#pragma unroll
    for (int i = 0; i < 4; i++)
#pragma unroll
        for (int j = 0; j < 8; j++) c2[i][j] = 0ull;

    float4 pra[2], prb[2];   // prefetch registers (mode1 uses them as 8 scalars each)

    auto loadA = [&](int kt) {
        if constexpr (MODE == 0) {
#pragma unroll
            for (int j = 0; j < 2; j++) {
                int idx = tid + 256 * j;
                int row = idx >> 2, kq = (idx & 3) << 2;
                int gm = m0 + row;
                pra[j] = (gm < M) ? *(const float4*)(g_accum + (size_t)gm * 256 + kt * 16 + kq)
                                  : make_float4(0.f, 0.f, 0.f, 0.f);
            }
        } else {
            float* pae = (float*)pra;
#pragma unroll
            for (int j = 0; j < 8; j++) {
                int idx = tid + 256 * j;
                int row = idx >> 4, kl = idx & 15;
                int gm = m0 + row, gk = kt * 16 + kl;
                float v = 0.f;
                if (gm < M && gk < KOUT)
                    v = (gk < AFD) ? node_x[(size_t)gm * AFD + gk]
                                   : g_mplus[(size_t)gm * 256 + (gk - AFD)];
                pae[j] = v;
            }
        }
    };
    auto loadB = [&](int kt) {
        if constexpr (MODE == 0) {
#pragma unroll
            for (int j = 0; j < 2; j++) {
                int idx = tid + 256 * j;
                int kr = idx >> 5, nq = (idx & 31) << 2;
                prb[j] = *(const float4*)(B + (size_t)(kt * 16 + kr) * 256 + n0 + nq);
            }
        } else {
            float* pbe = (float*)prb;
#pragma unroll
            for (int j = 0; j < 8; j++) {
                int idx = tid + 256 * j;
                int kl = idx >> 7, n = idx & 127;
                int gk = kt * 16 + kl;
                pbe[j] = (gk < KOUT) ? B[(size_t)gk * 256 + n0 + n] : 0.f;
            }
        }
    };
    auto storeAB = [&]() {
        if constexpr (MODE == 0) {
#pragma unroll
            for (int j = 0; j < 2; j++) {
                int idx = tid + 256 * j;
                int row = idx >> 2, kq = (idx & 3) << 2;
                As[kq + 0][row] = pra[j].x;
                As[kq + 1][row] = pra[j].y;
                As[kq + 2][row] = pra[j].z;
                As[kq + 3][row] = pra[j].w;
            }
#pragma unroll
            for (int j = 0; j < 2; j++) {
                int idx = tid + 256 * j;
                int kr = idx >> 5, nq = (idx & 31) << 2;
                *(float4*)&Bs[kr][nq] = prb[j];
            }
        } else {
            const float* pae = (const float*)pra;
            const float* pbe = (const float*)prb;
#pragma unroll
            for (int j = 0; j < 8; j++) {
                int idx = tid + 256 * j;
                As[idx & 15][idx >> 4] = pae[j];
            }
#pragma unroll
            for (int j = 0; j < 8; j++) {
                int idx = tid + 256 * j;
                Bs[idx >> 7][idx & 127] = pbe[j];
            }
        }
    };

    loadA(0); loadB(0);
    storeAB();
    __syncthreads();

    for (int kt = 0; kt < KT; kt++) {
        bool more = (kt + 1 < KT);
        if (more) { loadA(kt + 1); loadB(kt + 1); }   // overlap gmem with compute
#pragma unroll
        for (int k = 0; k < 16; k++) {
            float4 a0 = *(const float4*)&As[k][ty * 4];
            float4 a1 = *(const float4*)&As[k][64 + ty * 4];
            float4 b0 = *(const float4*)&Bs[k][tx * 4];
            float4 b1 = *(const float4*)&Bs[k][64 + tx * 4];
            unsigned long long av[4];
            av[0] = pk2(a0.x, a0.y);
            av[1] = pk2(a0.z, a0.w);
            av[2] = pk2(a1.x, a1.y);
            av[3] = pk2(a1.z, a1.w);
            float bv[8] = {b0.x, b0.y, b0.z, b0.w, b1.x, b1.y, b1.z, b1.w};
#pragma unroll
            for (int n = 0; n < 8; n++) {
                unsigned long long bd = pk2(bv[n], bv[n]);
                ffma2(c2[0][n], av[0], bd);
                ffma2(c2[1][n], av[1], bd);
                ffma2(c2[2][n], av[2], bd);
                ffma2(c2[3][n], av[3], bd);
            }
        }
        __syncthreads();
        if (more) storeAB();
        __syncthreads();
    }

    // epilogue: c2[mp][n] = (row rbase, row rbase+1) x col n
#pragma unroll
    for (int mp = 0; mp < 4; mp++) {
        int rbase = (mp < 2) ? (ty * 4 + mp * 2) : (64 + ty * 4 + (mp - 2) * 2);
        float lo[8], hi[8];
#pragma unroll
        for (int n = 0; n < 8; n++) upk2(c2[mp][n], lo[n], hi[n]);
#pragma unroll
        for (int h = 0; h < 2; h++) {
            int gr = m0 + rbase + h;
            if (gr >= M) continue;
            const float* v = h ? hi : lo;
            size_t rb = (size_t)gr * 256 + n0;
            if constexpr (MODE == 0) {
                float4 mi0 = *(const float4*)(g_msg_input + rb + tx * 4);
                float4 mi1 = *(const float4*)(g_msg_input + rb + 64 + tx * 4);
                float4 o0, o1;
                o0.x = fmaxf(mi0.x + v[0], 0.f);
                o0.y = fmaxf(mi0.y + v[1], 0.f);
                o0.z = fmaxf(mi0.z + v[2], 0.f);
                o0.w = fmaxf(mi0.w + v[3], 0.f);
                o1.x = fmaxf(mi1.x + v[4], 0.f);
                o1.y = fmaxf(mi1.y + v[5], 0.f);
                o1.z = fmaxf(mi1.z + v[6], 0.f);
                o1.w = fmaxf(mi1.w + v[7], 0.f);
                *(float4*)(g_msg + rb + tx * 4)      = o0;
                *(float4*)(g_msg + rb + 64 + tx * 4) = o1;
            } else {
                float4 bb0 = *(const float4*)(b_o + n0 + tx * 4);
                float4 bb1 = *(const float4*)(b_o + n0 + 64 + tx * 4);
                int g = gids[gr];
                float* gp = out + (size_t)g * 256 + n0;
                red4(gp + tx * 4,
                     fmaxf(v[0] + bb0.x, 0.f), fmaxf(v[1] + bb0.y, 0.f),
                     fmaxf(v[2] + bb0.z, 0.f), fmaxf(v[3] + bb0.w, 0.f));
                red4(gp + 64 + tx * 4,
                     fmaxf(v[4] + bb1.x, 0.f), fmaxf(v[5] + bb1.y, 0.f),
                     fmaxf(v[6] + bb1.z, 0.f), fmaxf(v[7] + bb1.w, 0.f));
            }
        }
    }
}

// ---------------- launch ----------------
extern "C" void kernel_launch(void* const* d_in, const int* in_sizes, int n_in,
                              void* d_out, int out_size) {
    (void)in_sizes; (void)n_in; (void)out_size;
    const float* node_x = (const float*)d_in[0];
    const float* bond_x = (const float*)d_in[1];
    const float* tree   = (const float*)d_in[2];
    const float* W_i    = (const float*)d_in[3];
    const float* W_h    = (const float*)d_in[4];
    const float* W_o    = (const float*)d_in[5];
    const float* b_o    = (const float*)d_in[6];
    const int* esrc = (const int*)d_in[7];
    const int* edst = (const int*)d_in[8];
    const int* lsrc = (const int*)d_in[9];
    const int* ldst = (const int*)d_in[10];
    const int* tgt  = (const int*)d_in[11];
    const int* gids = (const int*)d_in[12];
    float* out = (float*)d_out;

    k_zero_alpha<<<37500, 256>>>();                       // 150000*64/256
    k_zero_out<<<512, 256>>>(out);                        // 2048*64/256
    k_tree_scatter<<<15000, 256>>>(tree, tgt);            // 60000*64/256
    k_msg_in<<<(N_EDGES_C + 63) / 64, 256>>>(node_x, bond_x, W_i, esrc);

    for (int it = 0; it < 3; it++) {                      // DEPTH-1
        k_gather_alpha<<<75000, 256>>>(esrc);             // 300000*64/256
        k_lg_scatter<<<150000, 256>>>(lsrc, ldst);        // 600000*64/256
        k_gemm<0><<<dim3(2344, 2), 256>>>(W_h, nullptr, nullptr, nullptr, nullptr);
    }

    k_copy_mplus<<<37500, 256>>>();
    k_dst_scatter<<<75000, 256>>>(edst);
    k_counts<<<586, 256>>>(gids);
    k_gemm<1><<<dim3(1172, 2), 256>>>(W_o, node_x, b_o, gids, out);
    k_div<<<512, 256>>>(out);
}

// round 3
// speedup vs baseline: 1.3960x; 1.3960x over previous
#include <cuda_runtime.h>
#include <cuda_fp16.h>
#include <cstdint>

#define N_NODES_C 150000
#define N_EDGES_C 300000
#define N_LG_C    600000
#define N_TREE_C  60000
#define HID       256
#define NGRAPH    2048
#define AFD       35
#define BFD       5
#define KIN       40

// ---------------- scratch (static device globals; no allocation) ----------------
__device__ float g_msg_input[(size_t)N_EDGES_C * HID];
__device__ float g_msg      [(size_t)N_EDGES_C * HID];
__device__ float g_accum    [(size_t)N_EDGES_C * HID];
__device__ float g_alpha    [(size_t)N_NODES_C * HID];
__device__ float g_mplus    [(size_t)N_NODES_C * HID];
__device__ float g_hbias    [(size_t)N_NODES_C * HID];
__device__ float g_WhT      [HID * HID];   // W_h transposed [n][k]
__device__ float g_WoT      [HID * HID];   // W_o rows 35..290 transposed [n][k]
__device__ float g_counts   [NGRAPH];

// ---------------- PTX helpers (portable: sm_80/sm_90 level only) ----------------
__device__ __forceinline__ uint32_t smem_u32(const void* p) {
    uint32_t a;
    asm("{ .reg .u64 t; cvta.to.shared.u64 t, %1; cvt.u32.u64 %0, t; }" : "=r"(a) : "l"(p));
    return a;
}
__device__ __forceinline__ void red4(float* p, float a, float b, float c, float d) {
    asm volatile("red.global.add.v4.f32 [%0], {%1, %2, %3, %4};"
                 :: "l"(p), "f"(a), "f"(b), "f"(c), "f"(d) : "memory");
}
__device__ __forceinline__ void red2(float* p, float a, float b) {
    asm volatile("red.global.add.v2.f32 [%0], {%1, %2};"
                 :: "l"(p), "f"(a), "f"(b) : "memory");
}
__device__ __forceinline__ void ldsm4(uint32_t* r, uint32_t addr) {
    asm volatile("ldmatrix.sync.aligned.m8n8.x4.shared.b16 {%0,%1,%2,%3}, [%4];"
                 : "=r"(r[0]), "=r"(r[1]), "=r"(r[2]), "=r"(r[3]) : "r"(addr));
}
__device__ __forceinline__ void ldsm2(uint32_t* r, uint32_t addr) {
    asm volatile("ldmatrix.sync.aligned.m8n8.x2.shared.b16 {%0,%1}, [%2];"
                 : "=r"(r[0]), "=r"(r[1]) : "r"(addr));
}
__device__ __forceinline__ void mma_f16(float* d, const uint32_t* a, const uint32_t* b) {
    asm volatile(
        "mma.sync.aligned.m16n8k16.row.col.f32.f16.f16.f32 "
        "{%0,%1,%2,%3}, {%4,%5,%6,%7}, {%8,%9}, {%0,%1,%2,%3};"
        : "+f"(d[0]), "+f"(d[1]), "+f"(d[2]), "+f"(d[3])
        : "r"(a[0]), "r"(a[1]), "r"(a[2]), "r"(a[3]), "r"(b[0]), "r"(b[1]));
}
__device__ __forceinline__ uint32_t h2u(__half2 h) { return *reinterpret_cast<uint32_t*>(&h); }

// ---------------- utility kernels ----------------
__global__ void k_zero_alpha() {
    int i = blockIdx.x * 256 + threadIdx.x;
    ((float4*)g_alpha)[i] = make_float4(0.f, 0.f, 0.f, 0.f);
}
__global__ void k_zero_out(float* __restrict__ out) {
    int i = blockIdx.x * 256 + threadIdx.x;
    ((float4*)out)[i] = make_float4(0.f, 0.f, 0.f, 0.f);
    if (i < NGRAPH) g_counts[i] = 0.f;
}
__global__ void k_copy_mplus() {
    int i = blockIdx.x * 256 + threadIdx.x;
    ((float4*)g_mplus)[i] = ((const float4*)g_alpha)[i];
}
__global__ void k_counts(const int* __restrict__ gids) {
    int v = blockIdx.x * 256 + threadIdx.x;
    if (v < N_NODES_C) atomicAdd(&g_counts[gids[v]], 1.0f);
}
__global__ void k_div(float* __restrict__ out) {
    int i = blockIdx.x * 256 + threadIdx.x;
    int g = i >> 6;
    float c = fmaxf(g_counts[g], 1.0f);
    float4 v = ((float4*)out)[i];
    v.x /= c; v.y /= c; v.z /= c; v.w /= c;
    ((float4*)out)[i] = v;
}
// WhT[n][k] = W_h[k][n]; WoT[n][k] = W_o[35+k][n]
__global__ void k_prep_w(const float* __restrict__ Wh, const float* __restrict__ Wo) {
    int n = blockIdx.x & 255;
    int k = threadIdx.x;
    if (blockIdx.x < 256) g_WhT[n * 256 + k] = Wh[k * 256 + n];
    else                  g_WoT[n * 256 + k] = Wo[(AFD + k) * 256 + n];
}
__global__ void k_tree_scatter(const float* __restrict__ tree, const int* __restrict__ tgt) {
    int i = blockIdx.x * 256 + threadIdx.x;
    int t = i >> 6, q = i & 63;
    float4 v = ((const float4*)tree)[(size_t)t * 64 + q];
    red4(g_alpha + (size_t)tgt[t] * HID + q * 4, v.x, v.y, v.z, v.w);
}
__global__ void k_gather_alpha(const int* __restrict__ esrc) {
    int i = blockIdx.x * 256 + threadIdx.x;
    int e = i >> 6, q = i & 63;
    ((float4*)g_accum)[(size_t)e * 64 + q] = ((const float4*)g_alpha)[(size_t)esrc[e] * 64 + q];
}
template<bool FIRST>
__global__ void k_lg_scatter(const int* __restrict__ lsrc, const int* __restrict__ ldst) {
    int i = blockIdx.x * 256 + threadIdx.x;
    int e = i >> 6, q = i & 63;
    const float4* src = FIRST ? (const float4*)g_msg_input : (const float4*)g_msg;
    float4 v = src[(size_t)lsrc[e] * 64 + q];
    if (FIRST) {
        v.x = fmaxf(v.x, 0.f); v.y = fmaxf(v.y, 0.f);
        v.z = fmaxf(v.z, 0.f); v.w = fmaxf(v.w, 0.f);
    }
    red4(g_accum + (size_t)ldst[e] * HID + q * 4, v.x, v.y, v.z, v.w);
}
__global__ void k_dst_scatter(const int* __restrict__ edst) {
    int i = blockIdx.x * 256 + threadIdx.x;
    int e = i >> 6, q = i & 63;
    float4 v = ((const float4*)g_msg)[(size_t)e * 64 + q];
    red4(g_mplus + (size_t)edst[e] * HID + q * 4, v.x, v.y, v.z, v.w);
}

// ---------------- msg_input = [node_x[src]; bond_x] @ W_i ----------------
__global__ __launch_bounds__(256)
void k_msg_in(const float* __restrict__ node_x, const float* __restrict__ bond_x,
              const float* __restrict__ W_i, const int* __restrict__ esrc) {
    __shared__ float feat[64][KIN];
    int e0 = blockIdx.x * 64;
    int tid = threadIdx.x;
    float w[KIN];
#pragma unroll
    for (int k = 0; k < KIN; k++) w[k] = W_i[k * HID + tid];
    for (int idx = tid; idx < 64 * KIN; idx += 256) {
        int e = idx / KIN, k = idx % KIN;
        int ge = e0 + e;
        float vv = 0.f;
        if (ge < N_EDGES_C)
            vv = (k < AFD) ? node_x[(size_t)esrc[ge] * AFD + k]
                           : bond_x[(size_t)ge * BFD + (k - AFD)];
        feat[e][k] = vv;
    }
    __syncthreads();
    for (int e = 0; e < 64; e++) {
        int ge = e0 + e;
        if (ge >= N_EDGES_C) break;
        float a0 = 0.f, a1 = 0.f;
#pragma unroll
        for (int k = 0; k < KIN; k += 2) {
            a0 = fmaf(feat[e][k],     w[k],     a0);
            a1 = fmaf(feat[e][k + 1], w[k + 1], a1);
        }
        g_msg_input[(size_t)ge * HID + tid] = a0 + a1;
    }
}

// ---------------- g_hbias = node_x @ W_o[:35] + b_o ----------------
__global__ __launch_bounds__(256)
void k_hbias(const float* __restrict__ node_x, const float* __restrict__ W_o,
             const float* __restrict__ b_o) {
    __shared__ float feat[64][AFD];
    int v0 = blockIdx.x * 64;
    int tid = threadIdx.x;
    float w[AFD];
#pragma unroll
    for (int k = 0; k < AFD; k++) w[k] = W_o[k * HID + tid];
    float bb = b_o[tid];
    for (int idx = tid; idx < 64 * AFD; idx += 256) {
        int v = idx / AFD, k = idx % AFD;
        int gv = v0 + v;
        feat[v][k] = (gv < N_NODES_C) ? node_x[(size_t)gv * AFD + k] : 0.f;
    }
    __syncthreads();
    for (int v = 0; v < 64; v++) {
        int gv = v0 + v;
        if (gv >= N_NODES_C) break;
        float a = bb;
#pragma unroll
        for (int k = 0; k < AFD; k++) a = fmaf(feat[v][k], w[k], a);
        g_hbias[(size_t)gv * HID + tid] = a;
    }
}

// ---------------- fp16-split tensor-core GEMM (mma.sync, portable) ----------------
// D[128,128 per CTA] = A[M,256] @ BT[256,256]^T, 2-term fp16 split (3 mma terms).
// MODE 0: g_msg = relu(bias + D)
// MODE 1: v = relu(bias + D); out[gids[row]] += v (red.v2)
// SMEM per buffer: Ah 16K | Al 16K | Bh 16K | Bl 16K = 64K; double-buffered = 128K.
#define KMM_SMEM (2 * 65536)

template<int MODE>
__global__ __launch_bounds__(512, 1)
void k_mm(const float* __restrict__ A, const float* __restrict__ bias,
          const float* __restrict__ BT, const int* __restrict__ gids,
          float* __restrict__ out, int M) {
    extern __shared__ char sm[];
    const int tid  = threadIdx.x;
    const int lane = tid & 31;
    const int wid  = tid >> 5;
    const int wm   = wid >> 2;       // 0..3  (M quadrant, 32 rows)
    const int wn   = wid & 3;        // 0..3  (N quadrant, 32 cols)
    const int m0   = blockIdx.x * 128;
    const int n0   = blockIdx.y * 128;
    const uint32_t sbase = smem_u32(sm);

    float d[2][4][4];
#pragma unroll
    for (int i = 0; i < 2; i++)
#pragma unroll
        for (int j = 0; j < 4; j++)
#pragma unroll
            for (int q = 0; q < 4; q++) d[i][j][q] = 0.f;

    float4 pfA[4], pfB[4];

    auto ldg = [&](int c) {
#pragma unroll
        for (int j = 0; j < 4; j++) {
            int idx = tid + j * 512;
            int row = idx >> 4, seg = idx & 15;
            pfA[j] = make_float4(0.f, 0.f, 0.f, 0.f);
            if (m0 + row < M)
                pfA[j] = *(const float4*)(A + (size_t)(m0 + row) * 256 + c * 64 + seg * 4);
            pfB[j] = *(const float4*)(BT + (size_t)(n0 + row) * 256 + c * 64 + seg * 4);
        }
    };
    auto sts = [&](int b) {
        char* buf = sm + b * 65536;
#pragma unroll
        for (int j = 0; j < 4; j++) {
            int idx = tid + j * 512;
            int row = idx >> 4, seg = idx & 15;
            uint32_t off = (uint32_t)(row * 128 + seg * 8);
            uint32_t sw = off ^ ((off >> 3) & 0x70);
            {
                float4 v = pfA[j];
                __half2 h01 = __floats2half2_rn(v.x, v.y);
                __half2 h23 = __floats2half2_rn(v.z, v.w);
                __half2 l01 = __floats2half2_rn(v.x - __low2float(h01), v.y - __high2float(h01));
                __half2 l23 = __floats2half2_rn(v.z - __low2float(h23), v.w - __high2float(h23));
                *(uint2*)(buf + sw)         = make_uint2(h2u(h01), h2u(h23));
                *(uint2*)(buf + 16384 + sw) = make_uint2(h2u(l01), h2u(l23));
            }
            {
                float4 v = pfB[j];
                __half2 h01 = __floats2half2_rn(v.x, v.y);
                __half2 h23 = __floats2half2_rn(v.z, v.w);
                __half2 l01 = __floats2half2_rn(v.x - __low2float(h01), v.y - __high2float(h01));
                __half2 l23 = __floats2half2_rn(v.z - __low2float(h23), v.w - __high2float(h23));
                *(uint2*)(buf + 32768 + sw) = make_uint2(h2u(h01), h2u(h23));
                *(uint2*)(buf + 49152 + sw) = make_uint2(h2u(l01), h2u(l23));
            }
        }
    };
    auto compute = [&](int b) {
        uint32_t base = sbase + b * 65536;
        const int r = lane & 7, q = lane >> 3;
#pragma unroll
        for (int s = 0; s < 4; s++) {
            uint32_t ah[2][4], al[2][4], bh[4][2], bl[4][2];
#pragma unroll
            for (int mt = 0; mt < 2; mt++) {
                uint32_t mrow = (uint32_t)(wm * 32 + mt * 16 + (q & 1) * 8 + r);
                uint32_t off = mrow * 128 + (q >> 1) * 16 + s * 32;
                uint32_t sw = off ^ ((off >> 3) & 0x70);
                ldsm4(ah[mt], base + sw);
                ldsm4(al[mt], base + 16384 + sw);
            }
#pragma unroll
            for (int nt = 0; nt < 4; nt++) {
                uint32_t nrow = (uint32_t)(wn * 32 + nt * 8 + r);
                uint32_t off = nrow * 128 + (q & 1) * 16 + s * 32;
                uint32_t sw = off ^ ((off >> 3) & 0x70);
                ldsm2(bh[nt], base + 32768 + sw);
                ldsm2(bl[nt], base + 49152 + sw);
            }
#pragma unroll
            for (int mt = 0; mt < 2; mt++)
#pragma unroll
                for (int nt = 0; nt < 4; nt++) {
                    mma_f16(d[mt][nt], ah[mt], bh[nt]);
                    mma_f16(d[mt][nt], ah[mt], bl[nt]);
                    mma_f16(d[mt][nt], al[mt], bh[nt]);
                }
        }
    };

    ldg(0); sts(0);
    __syncthreads();
#pragma unroll
    for (int c = 0; c < 4; c++) {
        if (c < 3) ldg(c + 1);          // prefetch overlaps mma loop
        compute(c & 1);
        if (c < 3) sts((c + 1) & 1);    // other buffer: no WAR hazard
        __syncthreads();
    }

    // epilogue
#pragma unroll
    for (int mt = 0; mt < 2; mt++) {
#pragma unroll
        for (int nt = 0; nt < 4; nt++) {
            int row = m0 + wm * 32 + mt * 16 + (lane >> 2);
            int col = n0 + wn * 32 + nt * 8 + (lane & 3) * 2;
#pragma unroll
            for (int h = 0; h < 2; h++) {
                int gr = row + h * 8;
                if (gr >= M) continue;
                size_t gb = (size_t)gr * 256 + col;
                float2 bv = *(const float2*)(bias + gb);
                float ox = fmaxf(bv.x + d[mt][nt][h * 2 + 0], 0.f);
                float oy = fmaxf(bv.y + d[mt][nt][h * 2 + 1], 0.f);
                if (MODE == 0) {
                    *(float2*)(g_msg + gb) = make_float2(ox, oy);
                } else {
                    int g = gids[gr];
                    red2(out + (size_t)g * 256 + col, ox, oy);
                }
            }
        }
    }
}

// ---------------- launch ----------------
extern "C" void kernel_launch(void* const* d_in, const int* in_sizes, int n_in,
                              void* d_out, int out_size) {
    (void)in_sizes; (void)n_in; (void)out_size;
    const float* node_x = (const float*)d_in[0];
    const float* bond_x = (const float*)d_in[1];
    const float* tree   = (const float*)d_in[2];
    const float* W_i    = (const float*)d_in[3];
    const float* W_h    = (const float*)d_in[4];
    const float* W_o    = (const float*)d_in[5];
    const float* b_o    = (const float*)d_in[6];
    const int* esrc = (const int*)d_in[7];
    const int* edst = (const int*)d_in[8];
    const int* lsrc = (const int*)d_in[9];
    const int* ldst = (const int*)d_in[10];
    const int* tgt  = (const int*)d_in[11];
    const int* gids = (const int*)d_in[12];
    float* out = (float*)d_out;

    cudaFuncSetAttribute(k_mm<0>, cudaFuncAttributeMaxDynamicSharedMemorySize, KMM_SMEM);
    cudaFuncSetAttribute(k_mm<1>, cudaFuncAttributeMaxDynamicSharedMemorySize, KMM_SMEM);

    float *WhT_p, *WoT_p, *hb_p, *acc_p, *mp_p, *mi_p;
    cudaGetSymbolAddress((void**)&WhT_p, g_WhT);
    cudaGetSymbolAddress((void**)&WoT_p, g_WoT);
    cudaGetSymbolAddress((void**)&hb_p,  g_hbias);
    cudaGetSymbolAddress((void**)&acc_p, g_accum);
    cudaGetSymbolAddress((void**)&mp_p,  g_mplus);
    cudaGetSymbolAddress((void**)&mi_p,  g_msg_input);

    k_prep_w<<<512, 256>>>(W_h, W_o);
    k_zero_alpha<<<37500, 256>>>();
    k_zero_out<<<512, 256>>>(out);
    k_tree_scatter<<<15000, 256>>>(tree, tgt);
    k_msg_in<<<(N_EDGES_C + 63) / 64, 256>>>(node_x, bond_x, W_i, esrc);
    k_hbias<<<(N_NODES_C + 63) / 64, 256>>>(node_x, W_o, b_o);

    for (int it = 0; it < 3; it++) {                      // DEPTH-1
        k_gather_alpha<<<75000, 256>>>(esrc);
        if (it == 0) k_lg_scatter<true><<<150000, 256>>>(lsrc, ldst);
        else         k_lg_scatter<false><<<150000, 256>>>(lsrc, ldst);
        k_mm<0><<<dim3(2344, 2), 512, KMM_SMEM>>>(acc_p, mi_p, WhT_p, nullptr, nullptr, N_EDGES_C);
    }

    k_copy_mplus<<<37500, 256>>>();
    k_dst_scatter<<<75000, 256>>>(edst);
    k_counts<<<586, 256>>>(gids);
    k_mm<1><<<dim3(1172, 2), 512, KMM_SMEM>>>(mp_p, hb_p, WoT_p, gids, out, N_NODES_C);
    k_div<<<512, 256>>>(out);
}

// round 6
// speedup vs baseline: 1.6867x; 1.2082x over previous
#include <cuda_runtime.h>
#include <cuda_fp16.h>
#include <cstdint>

#define N_NODES_C 150000
#define N_EDGES_C 300000
#define N_LG_C    600000
#define N_TREE_C  60000
#define HID       256
#define NGRAPH    2048
#define AFD       35
#define BFD       5
#define KIN       40

// ---------------- scratch (static device globals; no allocation) ----------------
__device__ float g_msg_input[(size_t)N_EDGES_C * HID];
__device__ float g_msg      [(size_t)N_EDGES_C * HID];
__device__ float g_accum    [(size_t)N_EDGES_C * HID];
__device__ float g_alpha    [(size_t)N_NODES_C * HID];
__device__ float g_mplus    [(size_t)N_NODES_C * HID];
__device__ float g_hbias    [(size_t)N_NODES_C * HID];
__device__ float g_WhT      [HID * HID];
__device__ float g_WoT      [HID * HID];
__device__ float g_counts   [NGRAPH];

// CSR structures
__device__ int g_lg_rowptr[N_EDGES_C + 1];
__device__ int g_lg_cursor[N_EDGES_C];      // doubles as histogram counts
__device__ int g_lg_csr[N_LG_C];
__device__ int g_nd_rowptr[N_NODES_C + 1];
__device__ int g_nd_cursor[N_NODES_C];
__device__ int g_nd_csr[N_EDGES_C];
__device__ int g_part [1024];
__device__ int g_part2[1024];

// ---------------- PTX helpers (portable: sm_80/sm_90 level only) ----------------
__device__ __forceinline__ uint32_t smem_u32(const void* p) {
    uint32_t a;
    asm("{ .reg .u64 t; cvta.to.shared.u64 t, %1; cvt.u32.u64 %0, t; }" : "=r"(a) : "l"(p));
    return a;
}
__device__ __forceinline__ void red4(float* p, float a, float b, float c, float d) {
    asm volatile("red.global.add.v4.f32 [%0], {%1, %2, %3, %4};"
                 :: "l"(p), "f"(a), "f"(b), "f"(c), "f"(d) : "memory");
}
__device__ __forceinline__ void red2(float* p, float a, float b) {
    asm volatile("red.global.add.v2.f32 [%0], {%1, %2};"
                 :: "l"(p), "f"(a), "f"(b) : "memory");
}
__device__ __forceinline__ void ldsm4(uint32_t* r, uint32_t addr) {
    asm volatile("ldmatrix.sync.aligned.m8n8.x4.shared.b16 {%0,%1,%2,%3}, [%4];"
                 : "=r"(r[0]), "=r"(r[1]), "=r"(r[2]), "=r"(r[3]) : "r"(addr));
}
__device__ __forceinline__ void ldsm2(uint32_t* r, uint32_t addr) {
    asm volatile("ldmatrix.sync.aligned.m8n8.x2.shared.b16 {%0,%1}, [%2];"
                 : "=r"(r[0]), "=r"(r[1]) : "r"(addr));
}
__device__ __forceinline__ void mma_f16(float* d, const uint32_t* a, const uint32_t* b) {
    asm volatile(
        "mma.sync.aligned.m16n8k16.row.col.f32.f16.f16.f32 "
        "{%0,%1,%2,%3}, {%4,%5,%6,%7}, {%8,%9}, {%0,%1,%2,%3};"
        : "+f"(d[0]), "+f"(d[1]), "+f"(d[2]), "+f"(d[3])
        : "r"(a[0]), "r"(a[1]), "r"(a[2]), "r"(a[3]), "r"(b[0]), "r"(b[1]));
}
__device__ __forceinline__ uint32_t h2u(__half2 h) { return *reinterpret_cast<uint32_t*>(&h); }

// ---------------- CSR build kernels ----------------
__global__ void k_zeroi(int* __restrict__ p, int n) {
    int i = blockIdx.x * 256 + threadIdx.x;
    if (i < n) p[i] = 0;
}
__global__ void k_hist(const int* __restrict__ dst, int* __restrict__ cnt, int n) {
    int i = blockIdx.x * 256 + threadIdx.x;
    if (i < n) atomicAdd(&cnt[dst[i]], 1);
}
// exclusive scan, 1024-elem chunks (256 thr x 4); part[b] = chunk total (optional)
__global__ void k_scan1(const int* __restrict__ cnt, int* __restrict__ ex, int n,
                        int* __restrict__ part) {
    __shared__ int sh[256];
    int base = blockIdx.x * 1024;
    int t = threadIdx.x;
    int v[4], s = 0;
#pragma unroll
    for (int j = 0; j < 4; j++) {
        int i = base + t * 4 + j;
        v[j] = (i < n) ? cnt[i] : 0;
        s += v[j];
    }
    sh[t] = s;
    __syncthreads();
    for (int off = 1; off < 256; off <<= 1) {
        int x = (t >= off) ? sh[t - off] : 0;
        __syncthreads();
        sh[t] += x;
        __syncthreads();
    }
    int run = (t > 0) ? sh[t - 1] : 0;
    if (part && t == 255) part[blockIdx.x] = sh[255];
#pragma unroll
    for (int j = 0; j < 4; j++) {
        int i = base + t * 4 + j;
        if (i < n) ex[i] = run;
        run += v[j];
    }
}
__global__ void k_scan3(int* __restrict__ ex, int* __restrict__ cursor,
                        const int* __restrict__ part2, int n, int ntot) {
    int i = blockIdx.x * 256 + threadIdx.x;
    if (i < n) {
        int v = ex[i] + part2[i >> 10];
        ex[i] = v;
        cursor[i] = v;
    }
    if (i == 0) ex[n] = ntot;
}
__global__ void k_fill(const int* __restrict__ src, const int* __restrict__ dst,
                       int* __restrict__ cursor, int* __restrict__ csr, int n) {
    int i = blockIdx.x * 256 + threadIdx.x;
    if (i < n) {
        int pos = atomicAdd(&cursor[dst[i]], 1);
        csr[pos] = src[i];
    }
}
// node CSR fill: csr[pos] = edge index i
__global__ void k_fill_id(const int* __restrict__ dst, int* __restrict__ cursor,
                          int* __restrict__ csr, int n) {
    int i = blockIdx.x * 256 + threadIdx.x;
    if (i < n) {
        int pos = atomicAdd(&cursor[dst[i]], 1);
        csr[pos] = i;
    }
}

// ---------------- utility kernels ----------------
__global__ void k_zero_alpha() {
    int i = blockIdx.x * 256 + threadIdx.x;
    ((float4*)g_alpha)[i] = make_float4(0.f, 0.f, 0.f, 0.f);
}
__global__ void k_zero_out(float* __restrict__ out) {
    int i = blockIdx.x * 256 + threadIdx.x;
    ((float4*)out)[i] = make_float4(0.f, 0.f, 0.f, 0.f);
    if (i < NGRAPH) g_counts[i] = 0.f;
}
__global__ void k_counts(const int* __restrict__ gids) {
    int v = blockIdx.x * 256 + threadIdx.x;
    if (v < N_NODES_C) atomicAdd(&g_counts[gids[v]], 1.0f);
}
__global__ void k_div(float* __restrict__ out) {
    int i = blockIdx.x * 256 + threadIdx.x;
    int g = i >> 6;
    float c = fmaxf(g_counts[g], 1.0f);
    float4 v = ((float4*)out)[i];
    v.x /= c; v.y /= c; v.z /= c; v.w /= c;
    ((float4*)out)[i] = v;
}
__global__ void k_prep_w(const float* __restrict__ Wh, const float* __restrict__ Wo) {
    int n = blockIdx.x & 255;
    int k = threadIdx.x;
    if (blockIdx.x < 256) g_WhT[n * 256 + k] = Wh[k * 256 + n];
    else                  g_WoT[n * 256 + k] = Wo[(AFD + k) * 256 + n];
}
__global__ void k_tree_scatter(const float* __restrict__ tree, const int* __restrict__ tgt) {
    int i = blockIdx.x * 256 + threadIdx.x;
    int t = i >> 6, q = i & 63;
    float4 v = ((const float4*)tree)[(size_t)t * 64 + q];
    red4(g_alpha + (size_t)tgt[t] * HID + q * 4, v.x, v.y, v.z, v.w);
}

// ---------------- CSR gather: accum[e] = alpha[esrc[e]] + sum msg[lg_csr[...]] --------
template<bool FIRST>
__global__ __launch_bounds__(256)
void k_lg_gather(const int* __restrict__ esrc) {
    int i = blockIdx.x * 256 + threadIdx.x;
    int e = i >> 6, q = i & 63;
    int a = __ldg(&esrc[e]);
    float4 acc = ((const float4*)g_alpha)[(size_t)a * 64 + q];
    int beg = __ldg(&g_lg_rowptr[e]);
    int end = __ldg(&g_lg_rowptr[e + 1]);
    const float4* src = FIRST ? (const float4*)g_msg_input : (const float4*)g_msg;
    for (int j = beg; j < end; j++) {
        int s = __ldg(&g_lg_csr[j]);
        float4 v = src[(size_t)s * 64 + q];
        if (FIRST) {
            v.x = fmaxf(v.x, 0.f); v.y = fmaxf(v.y, 0.f);
            v.z = fmaxf(v.z, 0.f); v.w = fmaxf(v.w, 0.f);
        }
        acc.x += v.x; acc.y += v.y; acc.z += v.z; acc.w += v.w;
    }
    ((float4*)g_accum)[(size_t)e * 64 + q] = acc;
}

// mplus[v] = alpha[v] + sum msg[nd_csr[...]]
__global__ __launch_bounds__(256)
void k_node_gather() {
    int i = blockIdx.x * 256 + threadIdx.x;
    int v = i >> 6, q = i & 63;
    float4 acc = ((const float4*)g_alpha)[(size_t)v * 64 + q];
    int beg = __ldg(&g_nd_rowptr[v]);
    int end = __ldg(&g_nd_rowptr[v + 1]);
    for (int j = beg; j < end; j++) {
        int s = __ldg(&g_nd_csr[j]);
        float4 m = ((const float4*)g_msg)[(size_t)s * 64 + q];
        acc.x += m.x; acc.y += m.y; acc.z += m.z; acc.w += m.w;
    }
    ((float4*)g_mplus)[(size_t)v * 64 + q] = acc;
}

// ---------------- msg_input = [node_x[src]; bond_x] @ W_i ----------------
__global__ __launch_bounds__(256)
void k_msg_in(const float* __restrict__ node_x, const float* __restrict__ bond_x,
              const float* __restrict__ W_i, const int* __restrict__ esrc) {
    __shared__ float feat[64][KIN];   // 160B rows, 16B aligned
    int e0 = blockIdx.x * 64;
    int tid = threadIdx.x;
    float w[KIN];
#pragma unroll
    for (int k = 0; k < KIN; k++) w[k] = W_i[k * HID + tid];
    for (int idx = tid; idx < 64 * KIN; idx += 256) {
        int e = idx / KIN, k = idx % KIN;
        int ge = e0 + e;
        float vv = 0.f;
        if (ge < N_EDGES_C)
            vv = (k < AFD) ? node_x[(size_t)esrc[ge] * AFD + k]
                           : bond_x[(size_t)ge * BFD + (k - AFD)];
        feat[e][k] = vv;
    }
    __syncthreads();
    for (int e = 0; e < 64; e++) {
        int ge = e0 + e;
        if (ge >= N_EDGES_C) break;
        const float4* f4 = (const float4*)feat[e];
        float a0 = 0.f, a1 = 0.f;
#pragma unroll
        for (int k4 = 0; k4 < KIN / 4; k4++) {
            float4 ff = f4[k4];
            a0 = fmaf(ff.x, w[k4 * 4 + 0], a0);
            a1 = fmaf(ff.y, w[k4 * 4 + 1], a1);
            a0 = fmaf(ff.z, w[k4 * 4 + 2], a0);
            a1 = fmaf(ff.w, w[k4 * 4 + 3], a1);
        }
        g_msg_input[(size_t)ge * HID + tid] = a0 + a1;
    }
}

// ---------------- g_hbias = node_x @ W_o[:35] + b_o ----------------
__global__ __launch_bounds__(256)
void k_hbias(const float* __restrict__ node_x, const float* __restrict__ W_o,
             const float* __restrict__ b_o) {
    __shared__ float feat[64][36];    // 144B rows, 16B aligned; col 35 = 0 pad
    int v0 = blockIdx.x * 64;
    int tid = threadIdx.x;
    float w[36];
#pragma unroll
    for (int k = 0; k < AFD; k++) w[k] = W_o[k * HID + tid];
    w[35] = 0.f;
    float bb = b_o[tid];
    for (int idx = tid; idx < 64 * 36; idx += 256) {
        int v = idx / 36, k = idx % 36;
        int gv = v0 + v;
        feat[v][k] = (gv < N_NODES_C && k < AFD) ? node_x[(size_t)gv * AFD + k] : 0.f;
    }
    __syncthreads();
    for (int v = 0; v < 64; v++) {
        int gv = v0 + v;
        if (gv >= N_NODES_C) break;
        const float4* f4 = (const float4*)feat[v];
        float a0 = bb, a1 = 0.f;
#pragma unroll
        for (int k4 = 0; k4 < 9; k4++) {
            float4 ff = f4[k4];
            a0 = fmaf(ff.x, w[k4 * 4 + 0], a0);
            a1 = fmaf(ff.y, w[k4 * 4 + 1], a1);
            a0 = fmaf(ff.z, w[k4 * 4 + 2], a0);
            a1 = fmaf(ff.w, w[k4 * 4 + 3], a1);
        }
        g_hbias[(size_t)gv * HID + tid] = a0 + a1;
    }
}

// ---------------- fp16-split tensor-core GEMM (mma.sync, portable) ----------------
#define KMM_SMEM (2 * 65536)

template<int MODE>
__global__ __launch_bounds__(512, 1)
void k_mm(const float* __restrict__ A, const float* __restrict__ bias,
          const float* __restrict__ BT, const int* __restrict__ gids,
          float* __restrict__ out, int M) {
    extern __shared__ char sm[];
    const int tid  = threadIdx.x;
    const int lane = tid & 31;
    const int wid  = tid >> 5;
    const int wm   = wid >> 2;
    const int wn   = wid & 3;
    const int m0   = blockIdx.x * 128;
    const int n0   = blockIdx.y * 128;
    const uint32_t sbase = smem_u32(sm);

    float d[2][4][4];
#pragma unroll
    for (int i = 0; i < 2; i++)
#pragma unroll
        for (int j = 0; j < 4; j++)
#pragma unroll
            for (int q = 0; q < 4; q++) d[i][j][q] = 0.f;

    float4 pfA[4], pfB[4];

    auto ldg = [&](int c) {
#pragma unroll
        for (int j = 0; j < 4; j++) {
            int idx = tid + j * 512;
            int row = idx >> 4, seg = idx & 15;
            pfA[j] = make_float4(0.f, 0.f, 0.f, 0.f);
            if (m0 + row < M)
                pfA[j] = *(const float4*)(A + (size_t)(m0 + row) * 256 + c * 64 + seg * 4);
            pfB[j] = *(const float4*)(BT + (size_t)(n0 + row) * 256 + c * 64 + seg * 4);
        }
    };
    auto sts = [&](int b) {
        char* buf = sm + b * 65536;
#pragma unroll
        for (int j = 0; j < 4; j++) {
            int idx = tid + j * 512;
            int row = idx >> 4, seg = idx & 15;
            uint32_t off = (uint32_t)(row * 128 + seg * 8);
            uint32_t sw = off ^ ((off >> 3) & 0x70);
            {
                float4 v = pfA[j];
                __half2 h01 = __floats2half2_rn(v.x, v.y);
                __half2 h23 = __floats2half2_rn(v.z, v.w);
                __half2 l01 = __floats2half2_rn(v.x - __low2float(h01), v.y - __high2float(h01));
                __half2 l23 = __floats2half2_rn(v.z - __low2float(h23), v.w - __high2float(h23));
                *(uint2*)(buf + sw)         = make_uint2(h2u(h01), h2u(h23));
                *(uint2*)(buf + 16384 + sw) = make_uint2(h2u(l01), h2u(l23));
            }
            {
                float4 v = pfB[j];
                __half2 h01 = __floats2half2_rn(v.x, v.y);
                __half2 h23 = __floats2half2_rn(v.z, v.w);
                __half2 l01 = __floats2half2_rn(v.x - __low2float(h01), v.y - __high2float(h01));
                __half2 l23 = __floats2half2_rn(v.z - __low2float(h23), v.w - __high2float(h23));
                *(uint2*)(buf + 32768 + sw) = make_uint2(h2u(h01), h2u(h23));
                *(uint2*)(buf + 49152 + sw) = make_uint2(h2u(l01), h2u(l23));
            }
        }
    };
    auto compute = [&](int b) {
        uint32_t base = sbase + b * 65536;
        const int r = lane & 7, q = lane >> 3;
#pragma unroll
        for (int s = 0; s < 4; s++) {
            uint32_t ah[2][4], al[2][4], bh[4][2], bl[4][2];
#pragma unroll
            for (int mt = 0; mt < 2; mt++) {
                uint32_t mrow = (uint32_t)(wm * 32 + mt * 16 + (q & 1) * 8 + r);
                uint32_t off = mrow * 128 + (q >> 1) * 16 + s * 32;
                uint32_t sw = off ^ ((off >> 3) & 0x70);
                ldsm4(ah[mt], base + sw);
                ldsm4(al[mt], base + 16384 + sw);
            }
#pragma unroll
            for (int nt = 0; nt < 4; nt++) {
                uint32_t nrow = (uint32_t)(wn * 32 + nt * 8 + r);
                uint32_t off = nrow * 128 + (q & 1) * 16 + s * 32;
                uint32_t sw = off ^ ((off >> 3) & 0x70);
                ldsm2(bh[nt], base + 32768 + sw);
                ldsm2(bl[nt], base + 49152 + sw);
            }
#pragma unroll
            for (int mt = 0; mt < 2; mt++)
#pragma unroll
                for (int nt = 0; nt < 4; nt++) {
                    mma_f16(d[mt][nt], ah[mt], bh[nt]);
                    mma_f16(d[mt][nt], ah[mt], bl[nt]);
                    mma_f16(d[mt][nt], al[mt], bh[nt]);
                }
        }
    };

    ldg(0); sts(0);
    __syncthreads();
#pragma unroll
    for (int c = 0; c < 4; c++) {
        if (c < 3) ldg(c + 1);
        compute(c & 1);
        if (c < 3) sts((c + 1) & 1);
        __syncthreads();
    }

#pragma unroll
    for (int mt = 0; mt < 2; mt++) {
#pragma unroll
        for (int nt = 0; nt < 4; nt++) {
            int row = m0 + wm * 32 + mt * 16 + (lane >> 2);
            int col = n0 + wn * 32 + nt * 8 + (lane & 3) * 2;
#pragma unroll
            for (int h = 0; h < 2; h++) {
                int gr = row + h * 8;
                if (gr >= M) continue;
                size_t gb = (size_t)gr * 256 + col;
                float2 bv = *(const float2*)(bias + gb);
                float ox = fmaxf(bv.x + d[mt][nt][h * 2 + 0], 0.f);
                float oy = fmaxf(bv.y + d[mt][nt][h * 2 + 1], 0.f);
                if (MODE == 0) {
                    *(float2*)(g_msg + gb) = make_float2(ox, oy);
                } else {
                    int g = gids[gr];
                    red2(out + (size_t)g * 256 + col, ox, oy);
                }
            }
        }
    }
}

// ---------------- launch ----------------
extern "C" void kernel_launch(void* const* d_in, const int* in_sizes, int n_in,
                              void* d_out, int out_size) {
    (void)in_sizes; (void)n_in; (void)out_size;
    const float* node_x = (const float*)d_in[0];
    const float* bond_x = (const float*)d_in[1];
    const float* tree   = (const float*)d_in[2];
    const float* W_i    = (const float*)d_in[3];
    const float* W_h    = (const float*)d_in[4];
    const float* W_o    = (const float*)d_in[5];
    const float* b_o    = (const float*)d_in[6];
    const int* esrc = (const int*)d_in[7];
    const int* edst = (const int*)d_in[8];
    const int* lsrc = (const int*)d_in[9];
    const int* ldst = (const int*)d_in[10];
    const int* tgt  = (const int*)d_in[11];
    const int* gids = (const int*)d_in[12];
    float* out = (float*)d_out;

    cudaFuncSetAttribute(k_mm<0>, cudaFuncAttributeMaxDynamicSharedMemorySize, KMM_SMEM);
    cudaFuncSetAttribute(k_mm<1>, cudaFuncAttributeMaxDynamicSharedMemorySize, KMM_SMEM);

    float *WhT_p, *WoT_p, *hb_p, *acc_p, *mp_p, *mi_p;
    cudaGetSymbolAddress((void**)&WhT_p, g_WhT);
    cudaGetSymbolAddress((void**)&WoT_p, g_WoT);
    cudaGetSymbolAddress((void**)&hb_p,  g_hbias);
    cudaGetSymbolAddress((void**)&acc_p, g_accum);
    cudaGetSymbolAddress((void**)&mp_p,  g_mplus);
    cudaGetSymbolAddress((void**)&mi_p,  g_msg_input);
    int *lg_rp, *lg_cur, *lg_csr_p, *nd_rp, *nd_cur, *nd_csr_p, *part_p, *part2_p;
    cudaGetSymbolAddress((void**)&lg_rp,    g_lg_rowptr);
    cudaGetSymbolAddress((void**)&lg_cur,   g_lg_cursor);
    cudaGetSymbolAddress((void**)&lg_csr_p, g_lg_csr);
    cudaGetSymbolAddress((void**)&nd_rp,    g_nd_rowptr);
    cudaGetSymbolAddress((void**)&nd_cur,   g_nd_cursor);
    cudaGetSymbolAddress((void**)&nd_csr_p, g_nd_csr);
    cudaGetSymbolAddress((void**)&part_p,   g_part);
    cudaGetSymbolAddress((void**)&part2_p,  g_part2);

    // ---- CSR build: line graph (buckets = ldst over N_EDGES) ----
    k_zeroi<<<1172, 256>>>(lg_cur, N_EDGES_C);
    k_hist<<<2344, 256>>>(ldst, lg_cur, N_LG_C);
    k_scan1<<<293, 256>>>(lg_cur, lg_rp, N_EDGES_C, part_p);
    k_scan1<<<1, 256>>>(part_p, part2_p, 293, nullptr);
    k_scan3<<<1172, 256>>>(lg_rp, lg_cur, part2_p, N_EDGES_C, N_LG_C);
    k_fill<<<2344, 256>>>(lsrc, ldst, lg_cur, lg_csr_p, N_LG_C);
    // ---- CSR build: node graph (buckets = edge_dst over N_NODES; values = edge id) ----
    k_zeroi<<<586, 256>>>(nd_cur, N_NODES_C);
    k_hist<<<1172, 256>>>(edst, nd_cur, N_EDGES_C);
    k_scan1<<<147, 256>>>(nd_cur, nd_rp, N_NODES_C, part_p);
    k_scan1<<<1, 256>>>(part_p, part2_p, 147, nullptr);
    k_scan3<<<586, 256>>>(nd_rp, nd_cur, part2_p, N_NODES_C, N_EDGES_C);
    k_fill_id<<<1172, 256>>>(edst, nd_cur, nd_csr_p, N_EDGES_C);

    k_prep_w<<<512, 256>>>(W_h, W_o);
    k_zero_alpha<<<37500, 256>>>();
    k_zero_out<<<512, 256>>>(out);
    k_tree_scatter<<<15000, 256>>>(tree, tgt);
    k_msg_in<<<(N_EDGES_C + 63) / 64, 256>>>(node_x, bond_x, W_i, esrc);
    k_hbias<<<(N_NODES_C + 63) / 64, 256>>>(node_x, W_o, b_o);

    for (int it = 0; it < 3; it++) {
        if (it == 0) k_lg_gather<true><<<75000, 256>>>(esrc);
        else         k_lg_gather<false><<<75000, 256>>>(esrc);
        k_mm<0><<<dim3(2344, 2), 512, KMM_SMEM>>>(acc_p, mi_p, WhT_p, nullptr, nullptr, N_EDGES_C);
    }

    k_node_gather<<<37500, 256>>>();
    k_counts<<<586, 256>>>(gids);
    k_mm<1><<<dim3(1172, 2), 512, KMM_SMEM>>>(mp_p, hb_p, WoT_p, gids, out, N_NODES_C);
    k_div<<<512, 256>>>(out);
}